// round 15
// baseline (speedup 1.0000x reference)
#include <cuda_runtime.h>
#include <cuda_fp16.h>
#include <cstdint>
#include <math.h>

#define DM   1024
#define DFF  286
#define SEG  288      // halves per relation segment
#define NP2  896      // P row stride in halves: [rel0@0 | rel1@288 | root@576 | pad]
#define ROOTOFF 576
#define YK   320      // padded d_ff for GEMM2 K (5 x BK)
#define MAXN 20000
#define MAXE 320000

#define BM 128
#define BN 128
#define BK 64         // halves per K chunk
#define SPAD 72       // smem row stride in halves
#define STAGE 18432   // halves per stage: (128+128)*72
#define NSTG 3

// fused_pre block ranges (M=20000 fixed)
#define RMS_BLKS  2500
#define PREP_BLKS 1024
#define DEG_BLKS  1250

// ---------------- scratch ----------------
__device__ __align__(16) __half g_Xn[(size_t)MAXN * DM];
__device__ __align__(16) __half g_Wcat[(size_t)NP2 * DM];    // [n][k] K-major, ln folded
__device__ __align__(16) __half g_WoT[(size_t)DM * YK];      // [n][k] K-major
__device__ __align__(16) __half g_P[(size_t)MAXN * NP2];     // fp16 projections
__device__ __align__(16) __half g_Y[(size_t)MAXN * YK];
__device__ int g_deg[MAXN * 2];
__device__ int g_cur[MAXN * 2];
__device__ int g_off[MAXN * 2];
__device__ int g_srcs[MAXE];
__device__ int g_alloc;

// ---------------- helpers ----------------
__device__ __forceinline__ void cp_async16(__half* smem_dst, const __half* gmem_src) {
    uint32_t s = (uint32_t)__cvta_generic_to_shared(smem_dst);
    asm volatile("cp.async.cg.shared.global [%0], [%1], 16;" :: "r"(s), "l"(gmem_src) : "memory");
}
#define CP_COMMIT() asm volatile("cp.async.commit_group;" ::: "memory")
#define CP_WAIT(n)  asm volatile("cp.async.wait_group %0;" :: "n"(n) : "memory")

// fp16-accumulator mma: D(f16x2 x2) = A*B + C(f16x2 x2)
__device__ __forceinline__ void mma_f16acc(uint32_t& c0, uint32_t& c1,
                                           uint32_t a0, uint32_t a1, uint32_t a2, uint32_t a3,
                                           uint32_t b0, uint32_t b1) {
    asm volatile("mma.sync.aligned.m16n8k16.row.col.f16.f16.f16.f16 "
                 "{%0,%1}, {%2,%3,%4,%5}, {%6,%7}, {%0,%1};"
                 : "+r"(c0), "+r"(c1)
                 : "r"(a0), "r"(a1), "r"(a2), "r"(a3), "r"(b0), "r"(b1));
}

// ---------------- fused pre-pass: rms+prescale | pack weights | deg ----------------
__global__ void __launch_bounds__(256) fused_pre(const float* __restrict__ x,
                                                 const float* __restrict__ W_rel,
                                                 const float* __restrict__ W_root,
                                                 const float* __restrict__ ln_w,
                                                 const float* __restrict__ wo,
                                                 const int* __restrict__ ei,
                                                 const int* __restrict__ et,
                                                 int M, int E) {
    int b = blockIdx.x;
    if (b < RMS_BLKS) {
        int row = (b * 256 + threadIdx.x) >> 5;
        int lane = threadIdx.x & 31;
        if (row >= M) return;
        const float4* xr = (const float4*)(x + (size_t)row * DM);
        float4 v[8];
        float s = 0.f;
        #pragma unroll
        for (int i = 0; i < 8; ++i) {
            v[i] = xr[lane + i * 32];
            s += v[i].x * v[i].x + v[i].y * v[i].y + v[i].z * v[i].z + v[i].w * v[i].w;
        }
        #pragma unroll
        for (int o = 16; o; o >>= 1) s += __shfl_xor_sync(0xffffffffu, s, o);
        float iv = rsqrtf(s * (1.0f / DM) + 1e-6f);
        uint2* yp = (uint2*)(g_Xn + (size_t)row * DM);
        #pragma unroll
        for (int i = 0; i < 8; ++i) {
            __half2 h0 = __floats2half2_rn(v[i].x * iv, v[i].y * iv);
            __half2 h1 = __floats2half2_rn(v[i].z * iv, v[i].w * iv);
            yp[lane + i * 32] = make_uint2(*(uint32_t*)&h0, *(uint32_t*)&h1);
        }
    } else if (b < RMS_BLKS + PREP_BLKS) {
        int bb = b - RMS_BLKS;
        if (bb == 0 && threadIdx.x == 0) g_alloc = 0;
        int nwc = NP2 * DM;
        int nwo = DM * YK;
        int total = nwc + nwo;
        for (int idx = bb * 256 + threadIdx.x; idx < total; idx += PREP_BLKS * 256) {
            if (idx < nwc) {
                int n = idx / DM, k = idx - n * DM;
                float v = 0.f;
                if (n < DFF)                                 v = W_rel[(size_t)k * DFF + n];
                else if (n >= SEG && n < SEG + DFF)          v = W_rel[(size_t)DM * DFF + (size_t)k * DFF + (n - SEG)];
                else if (n >= ROOTOFF && n < ROOTOFF + DFF)  v = W_root[(size_t)k * DFF + (n - ROOTOFF)];
                g_Wcat[idx] = __float2half_rn(v * ln_w[k]);
            } else {
                int i = idx - nwc;
                int n = i / YK, k = i - n * YK;
                float v = (k < DFF) ? wo[(size_t)k * DM + n] : 0.f;
                g_WoT[i] = __float2half_rn(v);
            }
        }
    } else {
        int e = (b - RMS_BLKS - PREP_BLKS) * 256 + threadIdx.x;
        if (e >= E) return;
        atomicAdd(&g_deg[ei[E + e] * 2 + et[e]], 1);
    }
}

// warp-aggregated slice allocator
__global__ void base_kernel(int n) {
    int i = blockIdx.x * blockDim.x + threadIdx.x;
    int lane = threadIdx.x & 31;
    int d = (i < n) ? g_deg[i] : 0;
    int pre = d;
    #pragma unroll
    for (int o = 1; o < 32; o <<= 1) {
        int v = __shfl_up_sync(0xffffffffu, pre, o);
        if (lane >= o) pre += v;
    }
    int warpsum = __shfl_sync(0xffffffffu, pre, 31);
    int base = 0;
    if (lane == 31) base = atomicAdd(&g_alloc, warpsum);
    base = __shfl_sync(0xffffffffu, base, 31);
    if (i < n) g_off[i] = base + pre - d;
}

__global__ void fill_kernel(const int* __restrict__ ei,
                            const int* __restrict__ et, int E) {
    int e = blockIdx.x * blockDim.x + threadIdx.x;
    if (e >= E) return;
    int b = ei[E + e] * 2 + et[e];
    int pos = atomicAdd(&g_cur[b], 1);
    g_srcs[g_off[b] + pos] = ei[e];
}

// zero g_deg/g_cur for the next replay (runs last in the graph)
__global__ void cleanup_kernel(int n) {
    int i = blockIdx.x * blockDim.x + threadIdx.x;
    if (i < n) { g_deg[i] = 0; g_cur[i] = 0; }
}

// ---------------- fp16 GEMM: block 128x128, 8 warps (2m x 4n), warp tile 64x32 ----------------
// fp16 accumulation within each K=64 chunk, promoted to fp32 per chunk.
template <int MODE>
__global__ void __launch_bounds__(256, 2) mma_gemm(float* __restrict__ Cout,
                                                   const float* __restrict__ resid,
                                                   int M) {
    constexpr int Kdim = MODE ? YK : DM;
    constexpr int nch  = Kdim / BK;
    const __half* __restrict__ A = MODE ? g_Y : g_Xn;
    const __half* __restrict__ B = MODE ? g_WoT : g_Wcat;

    extern __shared__ __half sm[];
    const int tid  = threadIdx.x;
    const int lane = tid & 31;
    const int wid  = tid >> 5;       // 0..7
    const int wm   = wid & 1;
    const int wn   = wid >> 1;       // 0..3
    const int m0   = blockIdx.y * BM;
    const int n0   = blockIdx.x * BN;

    const int lrow = tid >> 3;       // 0..31
    const int lc8  = (tid & 7) * 8;
    const int g = lane >> 2, t = lane & 3;

    const __half* aptr[4];
    const __half* bptr[4];
    #pragma unroll
    for (int i = 0; i < 4; ++i) {
        int row = lrow + i * 32;
        int mm = m0 + row; if (mm >= M) mm = M - 1;
        aptr[i] = A + (size_t)mm * Kdim + lc8;
        bptr[i] = B + (size_t)(n0 + row) * Kdim + lc8;
    }

    #define PREFETCH(s, c) do {                                       \
        int k0_ = (c) * BK;                                           \
        __half* As_ = sm + (s) * STAGE;                               \
        __half* Bs_ = sm + (s) * STAGE + 9216;                        \
        _Pragma("unroll")                                             \
        for (int i = 0; i < 4; ++i) {                                 \
            int row = lrow + i * 32;                                  \
            cp_async16(As_ + row * SPAD + lc8, aptr[i] + k0_);        \
            cp_async16(Bs_ + row * SPAD + lc8, bptr[i] + k0_);        \
        }                                                             \
        CP_COMMIT();                                                  \
    } while (0)

    PREFETCH(0, 0);
    if (nch > 1) PREFETCH(1, 1);

    float acc[4][4][4];
    #pragma unroll
    for (int i = 0; i < 4; i++)
        #pragma unroll
        for (int j = 0; j < 4; j++)
            #pragma unroll
            for (int q = 0; q < 4; q++) acc[i][j][q] = 0.f;

    #pragma unroll 1
    for (int c = 0; c < nch; ++c) {
        const int st = c % NSTG;
        if (c + 1 < nch) CP_WAIT(1); else CP_WAIT(0);
        __syncthreads();

        if (c + 2 < nch) PREFETCH((c + 2) % NSTG, c + 2);

        const __half* As_ = sm + st * STAGE;
        const __half* Bs_ = sm + st * STAGE + 9216;

        // fp16 chunk accumulators
        uint32_t hacc[4][4][2];
        #pragma unroll
        for (int mf = 0; mf < 4; ++mf)
            #pragma unroll
            for (int nf = 0; nf < 4; ++nf) { hacc[mf][nf][0] = 0u; hacc[mf][nf][1] = 0u; }

        #pragma unroll
        for (int ks = 0; ks < 4; ++ks) {
            int kk = ks * 16;
            uint32_t a[4][4], b[4][2];
            #pragma unroll
            for (int mf = 0; mf < 4; ++mf) {
                int r0 = wm * 64 + mf * 16 + g;
                a[mf][0] = *(const uint32_t*)&As_[r0 * SPAD + kk + 2 * t];
                a[mf][1] = *(const uint32_t*)&As_[(r0 + 8) * SPAD + kk + 2 * t];
                a[mf][2] = *(const uint32_t*)&As_[r0 * SPAD + kk + 8 + 2 * t];
                a[mf][3] = *(const uint32_t*)&As_[(r0 + 8) * SPAD + kk + 8 + 2 * t];
            }
            #pragma unroll
            for (int nf = 0; nf < 4; ++nf) {
                int nr = wn * 32 + nf * 8 + g;
                b[nf][0] = *(const uint32_t*)&Bs_[nr * SPAD + kk + 2 * t];
                b[nf][1] = *(const uint32_t*)&Bs_[nr * SPAD + kk + 8 + 2 * t];
            }
            #pragma unroll
            for (int mf = 0; mf < 4; ++mf)
                #pragma unroll
                for (int nf = 0; nf < 4; ++nf)
                    mma_f16acc(hacc[mf][nf][0], hacc[mf][nf][1],
                               a[mf][0], a[mf][1], a[mf][2], a[mf][3],
                               b[nf][0], b[nf][1]);
        }
        // promote chunk to fp32
        #pragma unroll
        for (int mf = 0; mf < 4; ++mf)
            #pragma unroll
            for (int nf = 0; nf < 4; ++nf) {
                float2 lo = __half22float2(*(__half2*)&hacc[mf][nf][0]);
                float2 hi = __half22float2(*(__half2*)&hacc[mf][nf][1]);
                acc[mf][nf][0] += lo.x; acc[mf][nf][1] += lo.y;
                acc[mf][nf][2] += hi.x; acc[mf][nf][3] += hi.y;
            }
        __syncthreads();
    }
    #undef PREFETCH

    // epilogue
    #pragma unroll
    for (int mf = 0; mf < 4; ++mf) {
        int m = m0 + wm * 64 + mf * 16 + g;
        #pragma unroll
        for (int nf = 0; nf < 4; ++nf) {
            int n = n0 + wn * 32 + nf * 8 + t * 2;
            if (MODE) {
                if (m < M) {
                    const float2 h = *(const float2*)(resid + (size_t)m * DM + n);
                    float2 o = make_float2(acc[mf][nf][0] + h.x, acc[mf][nf][1] + h.y);
                    *(float2*)(Cout + (size_t)m * DM + n) = o;
                }
                if (m + 8 < M) {
                    const float2 h = *(const float2*)(resid + (size_t)(m + 8) * DM + n);
                    float2 o = make_float2(acc[mf][nf][2] + h.x, acc[mf][nf][3] + h.y);
                    *(float2*)(Cout + (size_t)(m + 8) * DM + n) = o;
                }
            } else {
                if (m < M) {
                    __half2 h = __floats2half2_rn(acc[mf][nf][0], acc[mf][nf][1]);
                    *(uint32_t*)(g_P + (size_t)m * NP2 + n) = *(uint32_t*)&h;
                }
                if (m + 8 < M) {
                    __half2 h = __floats2half2_rn(acc[mf][nf][2], acc[mf][nf][3]);
                    *(uint32_t*)(g_P + (size_t)(m + 8) * NP2 + n) = *(uint32_t*)&h;
                }
            }
        }
    }
}

// ---------------- CSR gather + combine fused: warp per dst, 2-way edge unroll ----------------
__global__ void __launch_bounds__(256) gather_kernel(const float* __restrict__ bias, int M) {
    int warp = (blockIdx.x * blockDim.x + threadIdx.x) >> 5;
    int lane = threadIdx.x & 31;
    if (warp >= M) return;
    int dst = warp;

    float2 acc[2][5];
    float cnt[2];
    #pragma unroll
    for (int r = 0; r < 2; ++r) {
        #pragma unroll
        for (int i = 0; i < 5; ++i) acc[r][i] = make_float2(0.f, 0.f);
        int beg = g_off[dst * 2 + r];
        int d   = g_deg[dst * 2 + r];
        cnt[r] = (float)d;
        int e = beg;
        for (; e + 1 < beg + d; e += 2) {
            int s0 = g_srcs[e], s1 = g_srcs[e + 1];
            const uint32_t* p0 = (const uint32_t*)(g_P + (size_t)s0 * NP2 + r * SEG);
            const uint32_t* p1 = (const uint32_t*)(g_P + (size_t)s1 * NP2 + r * SEG);
            #pragma unroll
            for (int i = 0; i < 5; ++i) {
                int w = lane + i * 32;
                if (w < SEG / 2) {
                    uint32_t b0 = p0[w], b1 = p1[w];
                    float2 f0 = __half22float2(*(__half2*)&b0);
                    float2 f1 = __half22float2(*(__half2*)&b1);
                    acc[r][i].x += f0.x + f1.x;
                    acc[r][i].y += f0.y + f1.y;
                }
            }
        }
        if (e < beg + d) {
            int s0 = g_srcs[e];
            const uint32_t* p0 = (const uint32_t*)(g_P + (size_t)s0 * NP2 + r * SEG);
            #pragma unroll
            for (int i = 0; i < 5; ++i) {
                int w = lane + i * 32;
                if (w < SEG / 2) {
                    uint32_t b0 = p0[w];
                    float2 f0 = __half22float2(*(__half2*)&b0);
                    acc[r][i].x += f0.x;
                    acc[r][i].y += f0.y;
                }
            }
        }
    }
    float ic0 = 1.f / fmaxf(cnt[0], 1.f), ic1 = 1.f / fmaxf(cnt[1], 1.f);
    const uint32_t* rootp = (const uint32_t*)(g_P + (size_t)dst * NP2 + ROOTOFF);
    uint32_t* yp = (uint32_t*)(g_Y + (size_t)dst * YK);
    #pragma unroll
    for (int i = 0; i < 5; ++i) {
        int w = lane + i * 32;
        float2 o = make_float2(0.f, 0.f);
        if (w < DFF / 2) {
            uint32_t rbits = rootp[w];
            float2 rt = __half22float2(*(__half2*)&rbits);
            int j = 2 * w;
            float x0 = rt.x + bias[j]     + acc[0][i].x * ic0 + acc[1][i].x * ic1;
            float x1 = rt.y + bias[j + 1] + acc[0][i].y * ic0 + acc[1][i].y * ic1;
            o.x = (x0 > 0.f) ? x0 : expm1f(x0);
            o.y = (x1 > 0.f) ? x1 : expm1f(x1);
        }
        __half2 h = __floats2half2_rn(o.x, o.y);
        yp[w] = *(uint32_t*)&h;
    }
}

#define GEMM_SMEM (NSTG * STAGE * 2)   // 110592 bytes

// ---------------- launch ----------------
extern "C" void kernel_launch(void* const* d_in, const int* in_sizes, int n_in,
                              void* d_out, int out_size) {
    const float* hidden    = (const float*)d_in[0];
    const int*   edge_idx  = (const int*)d_in[1];
    const int*   edge_type = (const int*)d_in[2];
    const float* ln_w      = (const float*)d_in[3];
    const float* W_rel     = (const float*)d_in[4];
    const float* W_root    = (const float*)d_in[5];
    const float* conv_bias = (const float*)d_in[6];
    const float* wo        = (const float*)d_in[7];
    float*       out       = (float*)d_out;

    int M = in_sizes[0] / DM;   // 20000
    int E = in_sizes[2];        // 320000

    cudaFuncSetAttribute(mma_gemm<0>, cudaFuncAttributeMaxDynamicSharedMemorySize, GEMM_SMEM);
    cudaFuncSetAttribute(mma_gemm<1>, cudaFuncAttributeMaxDynamicSharedMemorySize, GEMM_SMEM);

    fused_pre<<<RMS_BLKS + PREP_BLKS + DEG_BLKS, 256>>>(hidden, W_rel, W_root, ln_w, wo,
                                                        edge_idx, edge_type, M, E);
    base_kernel<<<(2 * M + 255) / 256, 256>>>(2 * M);
    fill_kernel<<<(E + 255) / 256, 256>>>(edge_idx, edge_type, E);

    dim3 g1(NP2 / BN, (M + BM - 1) / BM);
    mma_gemm<0><<<g1, 256, GEMM_SMEM>>>((float*)0, (const float*)0, M);

    gather_kernel<<<(M * 32 + 255) / 256, 256>>>(conv_bias, M);

    dim3 g2(DM / BN, (M + BM - 1) / BM);
    mma_gemm<1><<<g2, 256, GEMM_SMEM>>>(out, hidden, M);

    cleanup_kernel<<<(2 * M + 255) / 256, 256>>>(2 * M);
}

// round 16
// speedup vs baseline: 1.1560x; 1.1560x over previous
#include <cuda_runtime.h>
#include <cuda_fp16.h>
#include <cstdint>
#include <math.h>

#define DM   1024
#define DFF  286
#define SEG  288      // halves per relation segment
#define NP2  896      // P row stride in halves: [rel0@0 | rel1@288 | root@576 | pad]
#define ROOTOFF 576
#define YK   320      // padded d_ff for GEMM2 K (5 x BK)
#define MAXN 20000
#define MAXE 320000

#define BM 128
#define BN 128
#define BK 64         // halves per K chunk
#define SPAD 72       // smem row stride in halves (144B: ldmatrix rows 4 banks apart, conflict-free)
#define STAGE 18432   // halves per stage: (128+128)*72
#define NSTG 3

// fused_pre block ranges (M=20000 fixed)
#define RMS_BLKS  2500
#define PREP_BLKS 1024
#define DEG_BLKS  1250

// ---------------- scratch ----------------
__device__ __align__(16) __half g_Xn[(size_t)MAXN * DM];
__device__ __align__(16) __half g_Wcat[(size_t)NP2 * DM];    // [n][k] K-major, ln folded
__device__ __align__(16) __half g_WoT[(size_t)DM * YK];      // [n][k] K-major
__device__ __align__(16) __half g_P[(size_t)MAXN * NP2];     // fp16 projections
__device__ __align__(16) __half g_Y[(size_t)MAXN * YK];
__device__ int g_deg[MAXN * 2];
__device__ int g_cur[MAXN * 2];
__device__ int g_off[MAXN * 2];
__device__ int g_srcs[MAXE];
__device__ int g_alloc;

// ---------------- helpers ----------------
__device__ __forceinline__ void cp_async16(__half* smem_dst, const __half* gmem_src) {
    uint32_t s = (uint32_t)__cvta_generic_to_shared(smem_dst);
    asm volatile("cp.async.cg.shared.global [%0], [%1], 16;" :: "r"(s), "l"(gmem_src) : "memory");
}
#define CP_COMMIT() asm volatile("cp.async.commit_group;" ::: "memory")
#define CP_WAIT(n)  asm volatile("cp.async.wait_group %0;" :: "n"(n) : "memory")

__device__ __forceinline__ void mma_f16(float& c0, float& c1, float& c2, float& c3,
                                        uint32_t a0, uint32_t a1, uint32_t a2, uint32_t a3,
                                        uint32_t b0, uint32_t b1) {
    asm volatile("mma.sync.aligned.m16n8k16.row.col.f32.f16.f16.f32 "
                 "{%0,%1,%2,%3}, {%4,%5,%6,%7}, {%8,%9}, {%0,%1,%2,%3};"
                 : "+f"(c0), "+f"(c1), "+f"(c2), "+f"(c3)
                 : "r"(a0), "r"(a1), "r"(a2), "r"(a3), "r"(b0), "r"(b1));
}

__device__ __forceinline__ void ldsm_x4(uint32_t& r0, uint32_t& r1, uint32_t& r2, uint32_t& r3,
                                        uint32_t addr) {
    asm volatile("ldmatrix.sync.aligned.m8n8.x4.shared.b16 {%0,%1,%2,%3}, [%4];"
                 : "=r"(r0), "=r"(r1), "=r"(r2), "=r"(r3) : "r"(addr));
}

// ---------------- fused pre-pass: rms+prescale | pack weights | deg ----------------
__global__ void __launch_bounds__(256) fused_pre(const float* __restrict__ x,
                                                 const float* __restrict__ W_rel,
                                                 const float* __restrict__ W_root,
                                                 const float* __restrict__ ln_w,
                                                 const float* __restrict__ wo,
                                                 const int* __restrict__ ei,
                                                 const int* __restrict__ et,
                                                 int M, int E) {
    int b = blockIdx.x;
    if (b < RMS_BLKS) {
        int row = (b * 256 + threadIdx.x) >> 5;
        int lane = threadIdx.x & 31;
        if (row >= M) return;
        const float4* xr = (const float4*)(x + (size_t)row * DM);
        float4 v[8];
        float s = 0.f;
        #pragma unroll
        for (int i = 0; i < 8; ++i) {
            v[i] = xr[lane + i * 32];
            s += v[i].x * v[i].x + v[i].y * v[i].y + v[i].z * v[i].z + v[i].w * v[i].w;
        }
        #pragma unroll
        for (int o = 16; o; o >>= 1) s += __shfl_xor_sync(0xffffffffu, s, o);
        float iv = rsqrtf(s * (1.0f / DM) + 1e-6f);
        uint2* yp = (uint2*)(g_Xn + (size_t)row * DM);
        #pragma unroll
        for (int i = 0; i < 8; ++i) {
            __half2 h0 = __floats2half2_rn(v[i].x * iv, v[i].y * iv);
            __half2 h1 = __floats2half2_rn(v[i].z * iv, v[i].w * iv);
            yp[lane + i * 32] = make_uint2(*(uint32_t*)&h0, *(uint32_t*)&h1);
        }
    } else if (b < RMS_BLKS + PREP_BLKS) {
        int bb = b - RMS_BLKS;
        if (bb == 0 && threadIdx.x == 0) g_alloc = 0;
        int nwc = NP2 * DM;
        int nwo = DM * YK;
        int total = nwc + nwo;
        for (int idx = bb * 256 + threadIdx.x; idx < total; idx += PREP_BLKS * 256) {
            if (idx < nwc) {
                int n = idx / DM, k = idx - n * DM;
                float v = 0.f;
                if (n < DFF)                                 v = W_rel[(size_t)k * DFF + n];
                else if (n >= SEG && n < SEG + DFF)          v = W_rel[(size_t)DM * DFF + (size_t)k * DFF + (n - SEG)];
                else if (n >= ROOTOFF && n < ROOTOFF + DFF)  v = W_root[(size_t)k * DFF + (n - ROOTOFF)];
                g_Wcat[idx] = __float2half_rn(v * ln_w[k]);
            } else {
                int i = idx - nwc;
                int n = i / YK, k = i - n * YK;
                float v = (k < DFF) ? wo[(size_t)k * DM + n] : 0.f;
                g_WoT[i] = __float2half_rn(v);
            }
        }
    } else {
        int e = (b - RMS_BLKS - PREP_BLKS) * 256 + threadIdx.x;
        if (e >= E) return;
        atomicAdd(&g_deg[ei[E + e] * 2 + et[e]], 1);
    }
}

// warp-aggregated slice allocator
__global__ void base_kernel(int n) {
    int i = blockIdx.x * blockDim.x + threadIdx.x;
    int lane = threadIdx.x & 31;
    int d = (i < n) ? g_deg[i] : 0;
    int pre = d;
    #pragma unroll
    for (int o = 1; o < 32; o <<= 1) {
        int v = __shfl_up_sync(0xffffffffu, pre, o);
        if (lane >= o) pre += v;
    }
    int warpsum = __shfl_sync(0xffffffffu, pre, 31);
    int base = 0;
    if (lane == 31) base = atomicAdd(&g_alloc, warpsum);
    base = __shfl_sync(0xffffffffu, base, 31);
    if (i < n) g_off[i] = base + pre - d;
}

__global__ void fill_kernel(const int* __restrict__ ei,
                            const int* __restrict__ et, int E) {
    int e = blockIdx.x * blockDim.x + threadIdx.x;
    if (e >= E) return;
    int b = ei[E + e] * 2 + et[e];
    int pos = atomicAdd(&g_cur[b], 1);
    g_srcs[g_off[b] + pos] = ei[e];
}

// zero g_deg/g_cur for the next replay (runs last in the graph)
__global__ void cleanup_kernel(int n) {
    int i = blockIdx.x * blockDim.x + threadIdx.x;
    if (i < n) { g_deg[i] = 0; g_cur[i] = 0; }
}

// ---------------- fp16 GEMM: block 128x128, 8 warps (2m x 4n), warp tile 64x32 ----------------
// Fragment loads via ldmatrix.x4; fp32 accumulators.
template <int MODE>
__global__ void __launch_bounds__(256, 2) mma_gemm(float* __restrict__ Cout,
                                                   const float* __restrict__ resid,
                                                   int M) {
    constexpr int Kdim = MODE ? YK : DM;
    constexpr int nch  = Kdim / BK;
    const __half* __restrict__ A = MODE ? g_Y : g_Xn;
    const __half* __restrict__ B = MODE ? g_WoT : g_Wcat;

    extern __shared__ __half sm[];
    const int tid  = threadIdx.x;
    const int lane = tid & 31;
    const int wid  = tid >> 5;       // 0..7
    const int wm   = wid & 1;
    const int wn   = wid >> 1;       // 0..3
    const int m0   = blockIdx.y * BM;
    const int n0   = blockIdx.x * BN;

    const int lrow = tid >> 3;       // 0..31
    const int lc8  = (tid & 7) * 8;
    const int g = lane >> 2, t = lane & 3;

    const __half* aptr[4];
    const __half* bptr[4];
    #pragma unroll
    for (int i = 0; i < 4; ++i) {
        int row = lrow + i * 32;
        int mm = m0 + row; if (mm >= M) mm = M - 1;
        aptr[i] = A + (size_t)mm * Kdim + lc8;
        bptr[i] = B + (size_t)(n0 + row) * Kdim + lc8;
    }

    // ldmatrix lane-address components (in halves)
    const uint32_t smem_base = (uint32_t)__cvta_generic_to_shared(sm);
    // A: row = wm*64 + mf*16 + (lane&15), col = (lane>>4)*8
    const int a_row = wm * 64 + (lane & 15);
    const int a_col = (lane >> 4) * 8;
    // B: row = wn*32 + p*16 + (lane>>4)*8 + (lane&7), col = ((lane>>3)&1)*8
    const int b_row = wn * 32 + ((lane >> 4) << 3) + (lane & 7);
    const int b_col = ((lane >> 3) & 1) * 8;

    #define PREFETCH(s, c) do {                                       \
        int k0_ = (c) * BK;                                           \
        __half* As_ = sm + (s) * STAGE;                               \
        __half* Bs_ = sm + (s) * STAGE + 9216;                        \
        _Pragma("unroll")                                             \
        for (int i = 0; i < 4; ++i) {                                 \
            int row = lrow + i * 32;                                  \
            cp_async16(As_ + row * SPAD + lc8, aptr[i] + k0_);        \
            cp_async16(Bs_ + row * SPAD + lc8, bptr[i] + k0_);        \
        }                                                             \
        CP_COMMIT();                                                  \
    } while (0)

    PREFETCH(0, 0);
    if (nch > 1) PREFETCH(1, 1);

    float acc[4][4][4];
    #pragma unroll
    for (int i = 0; i < 4; i++)
        #pragma unroll
        for (int j = 0; j < 4; j++)
            #pragma unroll
            for (int q = 0; q < 4; q++) acc[i][j][q] = 0.f;

    #pragma unroll 1
    for (int c = 0; c < nch; ++c) {
        const int st = c % NSTG;
        if (c + 1 < nch) CP_WAIT(1); else CP_WAIT(0);
        __syncthreads();

        if (c + 2 < nch) PREFETCH((c + 2) % NSTG, c + 2);

        const uint32_t Asb = smem_base + (uint32_t)(st * STAGE) * 2u;
        const uint32_t Bsb = smem_base + (uint32_t)(st * STAGE + 9216) * 2u;

        #pragma unroll
        for (int ks = 0; ks < 4; ++ks) {
            int kk = ks * 16;
            uint32_t a[4][4], b[4][2];
            #pragma unroll
            for (int mf = 0; mf < 4; ++mf) {
                uint32_t ad = Asb + (uint32_t)(((a_row + mf * 16) * SPAD) + kk + a_col) * 2u;
                ldsm_x4(a[mf][0], a[mf][1], a[mf][2], a[mf][3], ad);
            }
            #pragma unroll
            for (int p = 0; p < 2; ++p) {
                uint32_t bd = Bsb + (uint32_t)(((b_row + p * 16) * SPAD) + kk + b_col) * 2u;
                ldsm_x4(b[2 * p][0], b[2 * p][1], b[2 * p + 1][0], b[2 * p + 1][1], bd);
            }
            #pragma unroll
            for (int mf = 0; mf < 4; ++mf)
                #pragma unroll
                for (int nf = 0; nf < 4; ++nf)
                    mma_f16(acc[mf][nf][0], acc[mf][nf][1], acc[mf][nf][2], acc[mf][nf][3],
                            a[mf][0], a[mf][1], a[mf][2], a[mf][3],
                            b[nf][0], b[nf][1]);
        }
        __syncthreads();
    }
    #undef PREFETCH

    // epilogue
    #pragma unroll
    for (int mf = 0; mf < 4; ++mf) {
        int m = m0 + wm * 64 + mf * 16 + g;
        #pragma unroll
        for (int nf = 0; nf < 4; ++nf) {
            int n = n0 + wn * 32 + nf * 8 + t * 2;
            if (MODE) {
                if (m < M) {
                    const float2 h = *(const float2*)(resid + (size_t)m * DM + n);
                    float2 o = make_float2(acc[mf][nf][0] + h.x, acc[mf][nf][1] + h.y);
                    *(float2*)(Cout + (size_t)m * DM + n) = o;
                }
                if (m + 8 < M) {
                    const float2 h = *(const float2*)(resid + (size_t)(m + 8) * DM + n);
                    float2 o = make_float2(acc[mf][nf][2] + h.x, acc[mf][nf][3] + h.y);
                    *(float2*)(Cout + (size_t)(m + 8) * DM + n) = o;
                }
            } else {
                if (m < M) {
                    __half2 h = __floats2half2_rn(acc[mf][nf][0], acc[mf][nf][1]);
                    *(uint32_t*)(g_P + (size_t)m * NP2 + n) = *(uint32_t*)&h;
                }
                if (m + 8 < M) {
                    __half2 h = __floats2half2_rn(acc[mf][nf][2], acc[mf][nf][3]);
                    *(uint32_t*)(g_P + (size_t)(m + 8) * NP2 + n) = *(uint32_t*)&h;
                }
            }
        }
    }
}

// ---------------- CSR gather + combine fused: warp per dst, 2-way edge unroll ----------------
__global__ void __launch_bounds__(256) gather_kernel(const float* __restrict__ bias, int M) {
    int warp = (blockIdx.x * blockDim.x + threadIdx.x) >> 5;
    int lane = threadIdx.x & 31;
    if (warp >= M) return;
    int dst = warp;

    float2 acc[2][5];
    float cnt[2];
    #pragma unroll
    for (int r = 0; r < 2; ++r) {
        #pragma unroll
        for (int i = 0; i < 5; ++i) acc[r][i] = make_float2(0.f, 0.f);
        int beg = g_off[dst * 2 + r];
        int d   = g_deg[dst * 2 + r];
        cnt[r] = (float)d;
        int e = beg;
        for (; e + 1 < beg + d; e += 2) {
            int s0 = g_srcs[e], s1 = g_srcs[e + 1];
            const uint32_t* p0 = (const uint32_t*)(g_P + (size_t)s0 * NP2 + r * SEG);
            const uint32_t* p1 = (const uint32_t*)(g_P + (size_t)s1 * NP2 + r * SEG);
            #pragma unroll
            for (int i = 0; i < 5; ++i) {
                int w = lane + i * 32;
                if (w < SEG / 2) {
                    uint32_t b0 = p0[w], b1 = p1[w];
                    float2 f0 = __half22float2(*(__half2*)&b0);
                    float2 f1 = __half22float2(*(__half2*)&b1);
                    acc[r][i].x += f0.x + f1.x;
                    acc[r][i].y += f0.y + f1.y;
                }
            }
        }
        if (e < beg + d) {
            int s0 = g_srcs[e];
            const uint32_t* p0 = (const uint32_t*)(g_P + (size_t)s0 * NP2 + r * SEG);
            #pragma unroll
            for (int i = 0; i < 5; ++i) {
                int w = lane + i * 32;
                if (w < SEG / 2) {
                    uint32_t b0 = p0[w];
                    float2 f0 = __half22float2(*(__half2*)&b0);
                    acc[r][i].x += f0.x;
                    acc[r][i].y += f0.y;
                }
            }
        }
    }
    float ic0 = 1.f / fmaxf(cnt[0], 1.f), ic1 = 1.f / fmaxf(cnt[1], 1.f);
    const uint32_t* rootp = (const uint32_t*)(g_P + (size_t)dst * NP2 + ROOTOFF);
    uint32_t* yp = (uint32_t*)(g_Y + (size_t)dst * YK);
    #pragma unroll
    for (int i = 0; i < 5; ++i) {
        int w = lane + i * 32;
        float2 o = make_float2(0.f, 0.f);
        if (w < DFF / 2) {
            uint32_t rbits = rootp[w];
            float2 rt = __half22float2(*(__half2*)&rbits);
            int j = 2 * w;
            float x0 = rt.x + bias[j]     + acc[0][i].x * ic0 + acc[1][i].x * ic1;
            float x1 = rt.y + bias[j + 1] + acc[0][i].y * ic0 + acc[1][i].y * ic1;
            o.x = (x0 > 0.f) ? x0 : expm1f(x0);
            o.y = (x1 > 0.f) ? x1 : expm1f(x1);
        }
        __half2 h = __floats2half2_rn(o.x, o.y);
        yp[w] = *(uint32_t*)&h;
    }
}

#define GEMM_SMEM (NSTG * STAGE * 2)   // 110592 bytes

// ---------------- launch ----------------
extern "C" void kernel_launch(void* const* d_in, const int* in_sizes, int n_in,
                              void* d_out, int out_size) {
    const float* hidden    = (const float*)d_in[0];
    const int*   edge_idx  = (const int*)d_in[1];
    const int*   edge_type = (const int*)d_in[2];
    const float* ln_w      = (const float*)d_in[3];
    const float* W_rel     = (const float*)d_in[4];
    const float* W_root    = (const float*)d_in[5];
    const float* conv_bias = (const float*)d_in[6];
    const float* wo        = (const float*)d_in[7];
    float*       out       = (float*)d_out;

    int M = in_sizes[0] / DM;   // 20000
    int E = in_sizes[2];        // 320000

    cudaFuncSetAttribute(mma_gemm<0>, cudaFuncAttributeMaxDynamicSharedMemorySize, GEMM_SMEM);
    cudaFuncSetAttribute(mma_gemm<1>, cudaFuncAttributeMaxDynamicSharedMemorySize, GEMM_SMEM);

    fused_pre<<<RMS_BLKS + PREP_BLKS + DEG_BLKS, 256>>>(hidden, W_rel, W_root, ln_w, wo,
                                                        edge_idx, edge_type, M, E);
    base_kernel<<<(2 * M + 255) / 256, 256>>>(2 * M);
    fill_kernel<<<(E + 255) / 256, 256>>>(edge_idx, edge_type, E);

    dim3 g1(NP2 / BN, (M + BM - 1) / BM);
    mma_gemm<0><<<g1, 256, GEMM_SMEM>>>((float*)0, (const float*)0, M);

    gather_kernel<<<(M * 32 + 255) / 256, 256>>>(conv_bias, M);

    dim3 g2(DM / BN, (M + BM - 1) / BM);
    mma_gemm<1><<<g2, 256, GEMM_SMEM>>>(out, hidden, M);

    cleanup_kernel<<<(2 * M + 255) / 256, 256>>>(2 * M);
}

// round 17
// speedup vs baseline: 1.1645x; 1.0074x over previous
#include <cuda_runtime.h>
#include <cuda_fp16.h>
#include <cstdint>
#include <math.h>

#define DM   1024
#define DFF  286
#define SEG  288      // halves per relation segment
#define NP2  896      // P row stride in halves: [rel0@0 | rel1@288 | root@576 | pad]
#define ROOTOFF 576
#define YK   320      // padded d_ff for GEMM2 K (5 x BK)
#define MAXN 20000
#define MAXE 320000

#define BM 128
#define BN 128
#define BK 64         // halves per K chunk
#define SPAD 72       // smem row stride in halves (144B: ldmatrix rows conflict-free)
#define STAGE 18432   // halves per stage: (128+128)*72
#define NSTG 3

// fused_pre block ranges (M=20000 fixed)
#define RMS_BLKS  2500
#define PREP_BLKS 1024
#define DEG_BLKS  1250

// ---------------- scratch ----------------
__device__ __align__(16) __half g_Xn[(size_t)MAXN * DM];
__device__ __align__(16) __half g_Wcat[(size_t)NP2 * DM];    // [n][k] K-major, ln folded
__device__ __align__(16) __half g_WoT[(size_t)DM * YK];      // [n][k] K-major
__device__ __align__(16) __half g_P[(size_t)MAXN * NP2];     // fp16 projections
__device__ __align__(16) __half g_Y[(size_t)MAXN * YK];
__device__ int g_deg[MAXN * 2];
__device__ int g_cur[MAXN * 2];
__device__ int g_off[MAXN * 2];
__device__ int g_srcs[MAXE];
__device__ int g_alloc;

// ---------------- helpers ----------------
__device__ __forceinline__ void cp_async16(__half* smem_dst, const __half* gmem_src) {
    uint32_t s = (uint32_t)__cvta_generic_to_shared(smem_dst);
    asm volatile("cp.async.cg.shared.global [%0], [%1], 16;" :: "r"(s), "l"(gmem_src) : "memory");
}
#define CP_COMMIT() asm volatile("cp.async.commit_group;" ::: "memory")
#define CP_WAIT(n)  asm volatile("cp.async.wait_group %0;" :: "n"(n) : "memory")

__device__ __forceinline__ void mma_f16(float& c0, float& c1, float& c2, float& c3,
                                        uint32_t a0, uint32_t a1, uint32_t a2, uint32_t a3,
                                        uint32_t b0, uint32_t b1) {
    asm volatile("mma.sync.aligned.m16n8k16.row.col.f32.f16.f16.f32 "
                 "{%0,%1,%2,%3}, {%4,%5,%6,%7}, {%8,%9}, {%0,%1,%2,%3};"
                 : "+f"(c0), "+f"(c1), "+f"(c2), "+f"(c3)
                 : "r"(a0), "r"(a1), "r"(a2), "r"(a3), "r"(b0), "r"(b1));
}

__device__ __forceinline__ void ldsm_x4(uint32_t& r0, uint32_t& r1, uint32_t& r2, uint32_t& r3,
                                        uint32_t addr) {
    asm volatile("ldmatrix.sync.aligned.m8n8.x4.shared.b16 {%0,%1,%2,%3}, [%4];"
                 : "=r"(r0), "=r"(r1), "=r"(r2), "=r"(r3) : "r"(addr));
}

// ---------------- fused pre-pass: rms+prescale | pack weights | deg ----------------
__global__ void __launch_bounds__(256) fused_pre(const float* __restrict__ x,
                                                 const float* __restrict__ W_rel,
                                                 const float* __restrict__ W_root,
                                                 const float* __restrict__ ln_w,
                                                 const float* __restrict__ wo,
                                                 const int* __restrict__ ei,
                                                 const int* __restrict__ et,
                                                 int M, int E) {
    int b = blockIdx.x;
    if (b < RMS_BLKS) {
        int row = (b * 256 + threadIdx.x) >> 5;
        int lane = threadIdx.x & 31;
        if (row >= M) return;
        const float4* xr = (const float4*)(x + (size_t)row * DM);
        float4 v[8];
        float s = 0.f;
        #pragma unroll
        for (int i = 0; i < 8; ++i) {
            v[i] = xr[lane + i * 32];
            s += v[i].x * v[i].x + v[i].y * v[i].y + v[i].z * v[i].z + v[i].w * v[i].w;
        }
        #pragma unroll
        for (int o = 16; o; o >>= 1) s += __shfl_xor_sync(0xffffffffu, s, o);
        float iv = rsqrtf(s * (1.0f / DM) + 1e-6f);
        uint2* yp = (uint2*)(g_Xn + (size_t)row * DM);
        #pragma unroll
        for (int i = 0; i < 8; ++i) {
            __half2 h0 = __floats2half2_rn(v[i].x * iv, v[i].y * iv);
            __half2 h1 = __floats2half2_rn(v[i].z * iv, v[i].w * iv);
            yp[lane + i * 32] = make_uint2(*(uint32_t*)&h0, *(uint32_t*)&h1);
        }
    } else if (b < RMS_BLKS + PREP_BLKS) {
        int bb = b - RMS_BLKS;
        if (bb == 0 && threadIdx.x == 0) g_alloc = 0;
        int nwc = NP2 * DM;
        int nwo = DM * YK;
        int total = nwc + nwo;
        for (int idx = bb * 256 + threadIdx.x; idx < total; idx += PREP_BLKS * 256) {
            if (idx < nwc) {
                int n = idx / DM, k = idx - n * DM;
                float v = 0.f;
                if (n < DFF)                                 v = W_rel[(size_t)k * DFF + n];
                else if (n >= SEG && n < SEG + DFF)          v = W_rel[(size_t)DM * DFF + (size_t)k * DFF + (n - SEG)];
                else if (n >= ROOTOFF && n < ROOTOFF + DFF)  v = W_root[(size_t)k * DFF + (n - ROOTOFF)];
                g_Wcat[idx] = __float2half_rn(v * ln_w[k]);
            } else {
                int i = idx - nwc;
                int n = i / YK, k = i - n * YK;
                float v = (k < DFF) ? wo[(size_t)k * DM + n] : 0.f;
                g_WoT[i] = __float2half_rn(v);
            }
        }
    } else {
        int e = (b - RMS_BLKS - PREP_BLKS) * 256 + threadIdx.x;
        if (e >= E) return;
        atomicAdd(&g_deg[ei[E + e] * 2 + et[e]], 1);
    }
}

// warp-aggregated slice allocator
__global__ void base_kernel(int n) {
    int i = blockIdx.x * blockDim.x + threadIdx.x;
    int lane = threadIdx.x & 31;
    int d = (i < n) ? g_deg[i] : 0;
    int pre = d;
    #pragma unroll
    for (int o = 1; o < 32; o <<= 1) {
        int v = __shfl_up_sync(0xffffffffu, pre, o);
        if (lane >= o) pre += v;
    }
    int warpsum = __shfl_sync(0xffffffffu, pre, 31);
    int base = 0;
    if (lane == 31) base = atomicAdd(&g_alloc, warpsum);
    base = __shfl_sync(0xffffffffu, base, 31);
    if (i < n) g_off[i] = base + pre - d;
}

__global__ void fill_kernel(const int* __restrict__ ei,
                            const int* __restrict__ et, int E) {
    int e = blockIdx.x * blockDim.x + threadIdx.x;
    if (e >= E) return;
    int b = ei[E + e] * 2 + et[e];
    int pos = atomicAdd(&g_cur[b], 1);
    g_srcs[g_off[b] + pos] = ei[e];
}

// zero g_deg/g_cur for the next replay (runs last in the graph)
__global__ void cleanup_kernel(int n) {
    int i = blockIdx.x * blockDim.x + threadIdx.x;
    if (i < n) { g_deg[i] = 0; g_cur[i] = 0; }
}

// ---------------- fp16 GEMM: block 128x128, 8 warps (2m x 4n), warp tile 64x32 ----------------
// ldmatrix fragment loads, fp32 accumulators, ONE sync per chunk.
template <int MODE>
__global__ void __launch_bounds__(256, 2) mma_gemm(float* __restrict__ Cout,
                                                   const float* __restrict__ resid,
                                                   int M) {
    constexpr int Kdim = MODE ? YK : DM;
    constexpr int nch  = Kdim / BK;
    const __half* __restrict__ A = MODE ? g_Y : g_Xn;
    const __half* __restrict__ B = MODE ? g_WoT : g_Wcat;

    extern __shared__ __half sm[];
    const int tid  = threadIdx.x;
    const int lane = tid & 31;
    const int wid  = tid >> 5;       // 0..7
    const int wm   = wid & 1;
    const int wn   = wid >> 1;       // 0..3
    const int m0   = blockIdx.y * BM;
    const int n0   = blockIdx.x * BN;

    const int lrow = tid >> 3;       // 0..31
    const int lc8  = (tid & 7) * 8;
    const int g = lane >> 2, t = lane & 3;

    const __half* aptr[4];
    const __half* bptr[4];
    #pragma unroll
    for (int i = 0; i < 4; ++i) {
        int row = lrow + i * 32;
        int mm = m0 + row; if (mm >= M) mm = M - 1;
        aptr[i] = A + (size_t)mm * Kdim + lc8;
        bptr[i] = B + (size_t)(n0 + row) * Kdim + lc8;
    }

    const uint32_t smem_base = (uint32_t)__cvta_generic_to_shared(sm);
    const int a_row = wm * 64 + (lane & 15);
    const int a_col = (lane >> 4) * 8;
    const int b_row = wn * 32 + ((lane >> 4) << 3) + (lane & 7);
    const int b_col = ((lane >> 3) & 1) * 8;

    #define PREFETCH(s, c) do {                                       \
        int k0_ = (c) * BK;                                           \
        __half* As_ = sm + (s) * STAGE;                               \
        __half* Bs_ = sm + (s) * STAGE + 9216;                        \
        _Pragma("unroll")                                             \
        for (int i = 0; i < 4; ++i) {                                 \
            int row = lrow + i * 32;                                  \
            cp_async16(As_ + row * SPAD + lc8, aptr[i] + k0_);        \
            cp_async16(Bs_ + row * SPAD + lc8, bptr[i] + k0_);        \
        }                                                             \
        CP_COMMIT();                                                  \
    } while (0)

    PREFETCH(0, 0);
    if (nch > 1) PREFETCH(1, 1);

    float acc[4][4][4];
    #pragma unroll
    for (int i = 0; i < 4; i++)
        #pragma unroll
        for (int j = 0; j < 4; j++)
            #pragma unroll
            for (int q = 0; q < 4; q++) acc[i][j][q] = 0.f;

    #pragma unroll 1
    for (int c = 0; c < nch; ++c) {
        const int st = c % NSTG;
        if (c + 1 < nch) CP_WAIT(1); else CP_WAIT(0);
        __syncthreads();   // single barrier: orders stage-c ready AND stage-(c-1) reads done

        if (c + 2 < nch) PREFETCH((c + 2) % NSTG, c + 2);

        const uint32_t Asb = smem_base + (uint32_t)(st * STAGE) * 2u;
        const uint32_t Bsb = smem_base + (uint32_t)(st * STAGE + 9216) * 2u;

        #pragma unroll
        for (int ks = 0; ks < 4; ++ks) {
            int kk = ks * 16;
            uint32_t a[4][4], b[4][2];
            #pragma unroll
            for (int mf = 0; mf < 4; ++mf) {
                uint32_t ad = Asb + (uint32_t)(((a_row + mf * 16) * SPAD) + kk + a_col) * 2u;
                ldsm_x4(a[mf][0], a[mf][1], a[mf][2], a[mf][3], ad);
            }
            #pragma unroll
            for (int p = 0; p < 2; ++p) {
                uint32_t bd = Bsb + (uint32_t)(((b_row + p * 16) * SPAD) + kk + b_col) * 2u;
                ldsm_x4(b[2 * p][0], b[2 * p][1], b[2 * p + 1][0], b[2 * p + 1][1], bd);
            }
            #pragma unroll
            for (int mf = 0; mf < 4; ++mf)
                #pragma unroll
                for (int nf = 0; nf < 4; ++nf)
                    mma_f16(acc[mf][nf][0], acc[mf][nf][1], acc[mf][nf][2], acc[mf][nf][3],
                            a[mf][0], a[mf][1], a[mf][2], a[mf][3],
                            b[nf][0], b[nf][1]);
        }
        // no trailing barrier: next iteration's top barrier provides the WAR ordering
    }
    #undef PREFETCH

    // epilogue
    #pragma unroll
    for (int mf = 0; mf < 4; ++mf) {
        int m = m0 + wm * 64 + mf * 16 + g;
        #pragma unroll
        for (int nf = 0; nf < 4; ++nf) {
            int n = n0 + wn * 32 + nf * 8 + t * 2;
            if (MODE) {
                if (m < M) {
                    const float2 h = *(const float2*)(resid + (size_t)m * DM + n);
                    float2 o = make_float2(acc[mf][nf][0] + h.x, acc[mf][nf][1] + h.y);
                    *(float2*)(Cout + (size_t)m * DM + n) = o;
                }
                if (m + 8 < M) {
                    const float2 h = *(const float2*)(resid + (size_t)(m + 8) * DM + n);
                    float2 o = make_float2(acc[mf][nf][2] + h.x, acc[mf][nf][3] + h.y);
                    *(float2*)(Cout + (size_t)(m + 8) * DM + n) = o;
                }
            } else {
                if (m < M) {
                    __half2 h = __floats2half2_rn(acc[mf][nf][0], acc[mf][nf][1]);
                    *(uint32_t*)(g_P + (size_t)m * NP2 + n) = *(uint32_t*)&h;
                }
                if (m + 8 < M) {
                    __half2 h = __floats2half2_rn(acc[mf][nf][2], acc[mf][nf][3]);
                    *(uint32_t*)(g_P + (size_t)(m + 8) * NP2 + n) = *(uint32_t*)&h;
                }
            }
        }
    }
}

// ---------------- CSR gather + combine fused: warp per dst, 2-way edge unroll ----------------
__global__ void __launch_bounds__(256) gather_kernel(const float* __restrict__ bias, int M) {
    int warp = (blockIdx.x * blockDim.x + threadIdx.x) >> 5;
    int lane = threadIdx.x & 31;
    if (warp >= M) return;
    int dst = warp;

    float2 acc[2][5];
    float cnt[2];
    #pragma unroll
    for (int r = 0; r < 2; ++r) {
        #pragma unroll
        for (int i = 0; i < 5; ++i) acc[r][i] = make_float2(0.f, 0.f);
        int beg = g_off[dst * 2 + r];
        int d   = g_deg[dst * 2 + r];
        cnt[r] = (float)d;
        int e = beg;
        for (; e + 1 < beg + d; e += 2) {
            int s0 = g_srcs[e], s1 = g_srcs[e + 1];
            const uint32_t* p0 = (const uint32_t*)(g_P + (size_t)s0 * NP2 + r * SEG);
            const uint32_t* p1 = (const uint32_t*)(g_P + (size_t)s1 * NP2 + r * SEG);
            #pragma unroll
            for (int i = 0; i < 5; ++i) {
                int w = lane + i * 32;
                if (w < SEG / 2) {
                    uint32_t b0 = p0[w], b1 = p1[w];
                    float2 f0 = __half22float2(*(__half2*)&b0);
                    float2 f1 = __half22float2(*(__half2*)&b1);
                    acc[r][i].x += f0.x + f1.x;
                    acc[r][i].y += f0.y + f1.y;
                }
            }
        }
        if (e < beg + d) {
            int s0 = g_srcs[e];
            const uint32_t* p0 = (const uint32_t*)(g_P + (size_t)s0 * NP2 + r * SEG);
            #pragma unroll
            for (int i = 0; i < 5; ++i) {
                int w = lane + i * 32;
                if (w < SEG / 2) {
                    uint32_t b0 = p0[w];
                    float2 f0 = __half22float2(*(__half2*)&b0);
                    acc[r][i].x += f0.x;
                    acc[r][i].y += f0.y;
                }
            }
        }
    }
    float ic0 = 1.f / fmaxf(cnt[0], 1.f), ic1 = 1.f / fmaxf(cnt[1], 1.f);
    const uint32_t* rootp = (const uint32_t*)(g_P + (size_t)dst * NP2 + ROOTOFF);
    uint32_t* yp = (uint32_t*)(g_Y + (size_t)dst * YK);
    #pragma unroll
    for (int i = 0; i < 5; ++i) {
        int w = lane + i * 32;
        float2 o = make_float2(0.f, 0.f);
        if (w < DFF / 2) {
            uint32_t rbits = rootp[w];
            float2 rt = __half22float2(*(__half2*)&rbits);
            int j = 2 * w;
            float x0 = rt.x + bias[j]     + acc[0][i].x * ic0 + acc[1][i].x * ic1;
            float x1 = rt.y + bias[j + 1] + acc[0][i].y * ic0 + acc[1][i].y * ic1;
            o.x = (x0 > 0.f) ? x0 : expm1f(x0);
            o.y = (x1 > 0.f) ? x1 : expm1f(x1);
        }
        __half2 h = __floats2half2_rn(o.x, o.y);
        yp[w] = *(uint32_t*)&h;
    }
}

#define GEMM_SMEM (NSTG * STAGE * 2)   // 110592 bytes

// ---------------- launch ----------------
extern "C" void kernel_launch(void* const* d_in, const int* in_sizes, int n_in,
                              void* d_out, int out_size) {
    const float* hidden    = (const float*)d_in[0];
    const int*   edge_idx  = (const int*)d_in[1];
    const int*   edge_type = (const int*)d_in[2];
    const float* ln_w      = (const float*)d_in[3];
    const float* W_rel     = (const float*)d_in[4];
    const float* W_root    = (const float*)d_in[5];
    const float* conv_bias = (const float*)d_in[6];
    const float* wo        = (const float*)d_in[7];
    float*       out       = (float*)d_out;

    int M = in_sizes[0] / DM;   // 20000
    int E = in_sizes[2];        // 320000

    cudaFuncSetAttribute(mma_gemm<0>, cudaFuncAttributeMaxDynamicSharedMemorySize, GEMM_SMEM);
    cudaFuncSetAttribute(mma_gemm<1>, cudaFuncAttributeMaxDynamicSharedMemorySize, GEMM_SMEM);

    fused_pre<<<RMS_BLKS + PREP_BLKS + DEG_BLKS, 256>>>(hidden, W_rel, W_root, ln_w, wo,
                                                        edge_idx, edge_type, M, E);
    base_kernel<<<(2 * M + 255) / 256, 256>>>(2 * M);
    fill_kernel<<<(E + 255) / 256, 256>>>(edge_idx, edge_type, E);

    dim3 g1(NP2 / BN, (M + BM - 1) / BM);
    mma_gemm<0><<<g1, 256, GEMM_SMEM>>>((float*)0, (const float*)0, M);

    gather_kernel<<<(M * 32 + 255) / 256, 256>>>(conv_bias, M);

    dim3 g2(DM / BN, (M + BM - 1) / BM);
    mma_gemm<1><<<g2, 256, GEMM_SMEM>>>(out, hidden, M);

    cleanup_kernel<<<(2 * M + 255) / 256, 256>>>(2 * M);
}